// round 8
// baseline (speedup 1.0000x reference)
#include <cuda_runtime.h>
#include <cuda_bf16.h>
#include <math.h>
#include <stdint.h>

#define N_UNIQ 20000
#define D_IN   128
#define D_OUT  384
#define K_NB   32
#define B_OUT  40000

#define KP        768          // split-K storage: [hi 384 | lo 384]
#define ROWS_PAD  20096        // 157 * 128
#define NCHUNK    36           // 3 segments x 12 chunks of BK=32
#define NGRP      4

// row-group boundaries (nodes) and M-tile boundaries
static const int g_node0[NGRP + 1] = {0, 5120, 10240, 15360, 20000};
static const int g_tile0[NGRP + 1] = {0, 40, 80, 120, 157};

// ---------------- scratch (__device__ globals) ------------------------------
__device__ __align__(128) __nv_bfloat16 g_Xs[ROWS_PAD * KP];  // A, hi|lo
__device__ __align__(128) __nv_bfloat16 g_Bt[D_OUT * KP];     // B [n][k], hi|lo
__device__ __align__(128) float g_c[D_OUT];                   // fused bias
__device__ __align__(128) float g_Z[ROWS_PAD * D_OUT];        // unnormalized out
__device__ __align__(128) float g_ssp[3 * ROWS_PAD];          // per-(yslab,row) sum sq

// ---------------- helpers ----------------------------------------------------
__device__ __forceinline__ uint32_t smem_u32(const void* p) {
    uint32_t a;
    asm("{ .reg .u64 t; cvta.to.shared.u64 t, %1; cvt.u32.u64 %0, t; }" : "=r"(a) : "l"(p));
    return a;
}
#define LDMATRIX_X4(r0, r1, r2, r3, addr) \
    asm volatile("ldmatrix.sync.aligned.m8n8.x4.shared.b16 {%0,%1,%2,%3}, [%4];" \
                 : "=r"(r0), "=r"(r1), "=r"(r2), "=r"(r3) : "r"(addr))
#define MMA_16816(d, a, b0, b1) \
    asm volatile("mma.sync.aligned.m16n8k16.row.col.f32.bf16.bf16.f32 " \
                 "{%0,%1,%2,%3}, {%4,%5,%6,%7}, {%8,%9}, {%0,%1,%2,%3};" \
                 : "+f"((d)[0]), "+f"((d)[1]), "+f"((d)[2]), "+f"((d)[3]) \
                 : "r"((a)[0]), "r"((a)[1]), "r"((a)[2]), "r"((a)[3]), \
                   "r"(b0), "r"(b1))
#define CP_ASYNC_16(dst, src) \
    asm volatile("cp.async.cg.shared.global [%0], [%1], 16;" :: "r"(dst), "l"(src))
#define CP_COMMIT() asm volatile("cp.async.commit_group;" ::: "memory")
#define CP_WAIT2()  asm volatile("cp.async.wait_group 2;" ::: "memory")

// ---------------------------------------------------------------------------
// Kernel 1: fused weight (transposed [n][k], bf16 hi|lo split) + fused bias.
// ---------------------------------------------------------------------------
__global__ __launch_bounds__(384) void combine_kernel(const float* __restrict__ Ws,
                               const float* __restrict__ Wa,
                               const float* __restrict__ Wd,
                               const float* __restrict__ WC,
                               const float* __restrict__ bias,
                               const float* __restrict__ WCb) {
    int j = threadIdx.x;      // output col n (0..383)
    int rb = blockIdx.x;      // 0..47 = 8-row groups, 48 = bias
    if (rb < 48) {
        int r0 = rb * 8;
        int part = r0 >> 7;
        const float* W = (part == 0) ? Ws : ((part == 1) ? Wa : Wd);
        __shared__ float sW[8][128];
        for (int t = j; t < 1024; t += 384) {
            int q = t >> 7, o = t & 127;
            sW[q][o] = W[((r0 & 127) + q) * 128 + o];
        }
        __syncthreads();
        float acc[8] = {0.f, 0.f, 0.f, 0.f, 0.f, 0.f, 0.f, 0.f};
#pragma unroll 4
        for (int o = 0; o < 128; o++) {
            float wc = __ldg(&WC[(part * 128 + o) * D_OUT + j]);
#pragma unroll
            for (int q = 0; q < 8; q++) acc[q] += sW[q][o] * wc;
        }
#pragma unroll
        for (int q = 0; q < 8; q++) {
            __nv_bfloat16 hi = __float2bfloat16(acc[q]);
            __nv_bfloat16 lo = __float2bfloat16(acc[q] - __bfloat162float(hi));
            g_Bt[j * KP + r0 + q] = hi;
            g_Bt[j * KP + 384 + r0 + q] = lo;
        }
    } else {
        float acc = WCb[j];
        for (int i = 0; i < D_OUT; i++)
            acc += bias[i] * WC[i * D_OUT + j];
        g_c[j] = acc;
    }
}

// ---------------------------------------------------------------------------
// Kernel 2: aggregation, warp-per-node (R6-proven body: float4 per lane,
// indices broadcast via shfl, fused adj/dis loop).
// ---------------------------------------------------------------------------
__global__ __launch_bounds__(256) void agg_kernel(const int* __restrict__ uniq,
                                                  const int* __restrict__ adj,
                                                  const int* __restrict__ dis,
                                                  const float* __restrict__ feat,
                                                  int node0) {
    const int warp = threadIdx.x >> 5;
    const int lane = threadIdx.x & 31;
    const int n = node0 + blockIdx.x * 8 + warp;

    const int ia = __ldg(&adj[n * K_NB + lane]);
    const int id = __ldg(&dis[n * K_NB + lane]);
    const int iu = __ldg(&uniq[n]);

    const float4* f4 = reinterpret_cast<const float4*>(feat);

    float4 a = make_float4(0.f, 0.f, 0.f, 0.f);
    float4 b = make_float4(0.f, 0.f, 0.f, 0.f);
#pragma unroll
    for (int k = 0; k < K_NB; k++) {
        int ra = __shfl_sync(0xffffffffu, ia, k);
        int rd = __shfl_sync(0xffffffffu, id, k);
        float4 va = __ldg(&f4[(size_t)ra * 32 + lane]);
        float4 vb = __ldg(&f4[(size_t)rd * 32 + lane]);
        a.x += va.x; a.y += va.y; a.z += va.z; a.w += va.w;
        b.x += vb.x; b.y += vb.y; b.z += vb.z; b.w += vb.w;
    }
    float4 sf = __ldg(&f4[(size_t)iu * 32 + lane]);
    const float inv = 1.f / 32.f;
    a.x *= inv; a.y *= inv; a.z *= inv; a.w *= inv;
    b.x *= inv; b.y *= inv; b.z *= inv; b.w *= inv;

    __nv_bfloat16* row = &g_Xs[(size_t)n * KP];
    auto store_seg = [&](int base, float4 v) {
        __nv_bfloat16 h[4], l[4];
        float vv[4] = {v.x, v.y, v.z, v.w};
#pragma unroll
        for (int q = 0; q < 4; q++) {
            h[q] = __float2bfloat16(vv[q]);
            l[q] = __float2bfloat16(vv[q] - __bfloat162float(h[q]));
        }
        *reinterpret_cast<uint2*>(&row[base + lane * 4])       = *reinterpret_cast<uint2*>(h);
        *reinterpret_cast<uint2*>(&row[384 + base + lane * 4]) = *reinterpret_cast<uint2*>(l);
    };
    store_seg(0, sf);
    store_seg(128, a);
    store_seg(256, b);
}

// ---------------------------------------------------------------------------
// Kernel 3: HMMA GEMM, 4-stage cp.async pipeline. Grid (tiles_g, 3).
// ---------------------------------------------------------------------------
#define LDROW   80
#define STG     (128 * LDROW)     // 10240 B per operand stage
#define SMEM_GEMM (4 * 2 * STG)   // 81920

__global__ __launch_bounds__(256, 2) void gemm_hmma(int tile0) {
    extern __shared__ __align__(128) char dsm[];
    const uint32_t sbase = smem_u32(dsm);
    const uint32_t aarea = sbase;
    const uint32_t barea = sbase + 4 * STG;

    const int tid   = threadIdx.x;
    const int lane  = tid & 31;
    const int wid   = tid >> 5;
    const int warpM = wid & 3;
    const int warpN = wid >> 2;
    const int row0  = (tile0 + blockIdx.x) * 128;
    const int n0    = blockIdx.y * 128;

    float acc[2][8][4];
#pragma unroll
    for (int mt = 0; mt < 2; mt++)
#pragma unroll
        for (int nt = 0; nt < 8; nt++)
#pragma unroll
            for (int q = 0; q < 4; q++) acc[mt][nt][q] = 0.f;

    const int ldr = tid >> 2;   // 0..63
    const int ldu = tid & 3;    // 0..3

    auto issue_stage = [&](int c) {
        int s = c & 3;
        int seg = c / 12, i = c % 12;
        int abase = ((seg == 1) ? 384 : 0) + i * 32;
        int bbase = ((seg == 2) ? 384 : 0) + i * 32;
        uint32_t da = aarea + s * STG;
        uint32_t db = barea + s * STG;
#pragma unroll
        for (int it = 0; it < 2; it++) {
            int r = ldr + it * 64;
            CP_ASYNC_16(da + r * LDROW + ldu * 16,
                        (const void*)&g_Xs[(size_t)(row0 + r) * KP + abase + ldu * 8]);
            CP_ASYNC_16(db + r * LDROW + ldu * 16,
                        (const void*)&g_Bt[(size_t)(n0 + r) * KP + bbase + ldu * 8]);
        }
    };

    const int lq = lane >> 3, lr = lane & 7;
    const int a_mrow = warpM * 32 + (lq & 1) * 8 + lr;
    const int a_koff = (lq >> 1) * 8;
    const int b_nrow = warpN * 64 + (lq >> 1) * 8 + lr;
    const int b_koff = (lq & 1) * 8;

#pragma unroll
    for (int s = 0; s < 3; s++) { issue_stage(s); CP_COMMIT(); }

    for (int c = 0; c < NCHUNK; c++) {
        CP_WAIT2();
        __syncthreads();
        if (c + 3 < NCHUNK) issue_stage(c + 3);
        CP_COMMIT();

        const int s = c & 3;
        const uint32_t abuf = aarea + s * STG;
        const uint32_t bbuf = barea + s * STG;
#pragma unroll
        for (int ks = 0; ks < 2; ks++) {
            uint32_t a[2][4];
#pragma unroll
            for (int mt = 0; mt < 2; mt++) {
                uint32_t addr = abuf + (a_mrow + mt * 16) * LDROW + (ks * 16 + a_koff) * 2;
                LDMATRIX_X4(a[mt][0], a[mt][1], a[mt][2], a[mt][3], addr);
            }
            uint32_t b[4][4];
#pragma unroll
            for (int np = 0; np < 4; np++) {
                uint32_t addr = bbuf + (b_nrow + np * 16) * LDROW + (ks * 16 + b_koff) * 2;
                LDMATRIX_X4(b[np][0], b[np][1], b[np][2], b[np][3], addr);
            }
#pragma unroll
            for (int mt = 0; mt < 2; mt++)
#pragma unroll
                for (int np = 0; np < 4; np++) {
                    MMA_16816(acc[mt][np * 2 + 0], a[mt], b[np][0], b[np][1]);
                    MMA_16816(acc[mt][np * 2 + 1], a[mt], b[np][2], b[np][3]);
                }
        }
    }

    // ---- epilogue ----
    const int g  = lane >> 2;
    const int cq = lane & 3;
    float ssA[2], ssB[2];
#pragma unroll
    for (int mt = 0; mt < 2; mt++) {
        const int rbase = row0 + warpM * 32 + mt * 16;
        float ss0 = 0.f, ss1 = 0.f;
#pragma unroll
        for (int nt = 0; nt < 8; nt++) {
            int col = n0 + warpN * 64 + nt * 8 + cq * 2;
            float b0 = __ldg(&g_c[col]);
            float b1 = __ldg(&g_c[col + 1]);
            float z0 = acc[mt][nt][0] + b0; z0 = (z0 >= 0.f) ? z0 : 0.2f * z0;
            float z1 = acc[mt][nt][1] + b1; z1 = (z1 >= 0.f) ? z1 : 0.2f * z1;
            float z2 = acc[mt][nt][2] + b0; z2 = (z2 >= 0.f) ? z2 : 0.2f * z2;
            float z3 = acc[mt][nt][3] + b1; z3 = (z3 >= 0.f) ? z3 : 0.2f * z3;
            *reinterpret_cast<float2*>(&g_Z[(size_t)(rbase + g) * D_OUT + col])     = make_float2(z0, z1);
            *reinterpret_cast<float2*>(&g_Z[(size_t)(rbase + g + 8) * D_OUT + col]) = make_float2(z2, z3);
            ss0 += z0 * z0 + z1 * z1;
            ss1 += z2 * z2 + z3 * z3;
        }
        ss0 += __shfl_xor_sync(0xffffffffu, ss0, 1);
        ss0 += __shfl_xor_sync(0xffffffffu, ss0, 2);
        ss1 += __shfl_xor_sync(0xffffffffu, ss1, 1);
        ss1 += __shfl_xor_sync(0xffffffffu, ss1, 2);
        ssA[mt] = ss0;
        ssB[mt] = ss1;
    }
    __syncthreads();
    float* s_ss = reinterpret_cast<float*>(dsm);
    if (tid < 128) s_ss[tid] = 0.f;
    __syncthreads();
    if (cq == 0) {
#pragma unroll
        for (int mt = 0; mt < 2; mt++) {
            atomicAdd(&s_ss[warpM * 32 + mt * 16 + g],     ssA[mt]);
            atomicAdd(&s_ss[warpM * 32 + mt * 16 + 8 + g], ssB[mt]);
        }
    }
    __syncthreads();
    if (tid < 128) g_ssp[(size_t)blockIdx.y * ROWS_PAD + row0 + tid] = s_ss[tid];
}

// ---------------------------------------------------------------------------
// Kernel 4: normalize + batch gather. Warp per output row, MLP 3.
// ---------------------------------------------------------------------------
__global__ __launch_bounds__(256) void gather_kernel(const int* __restrict__ nidx,
                                                     float* __restrict__ out) {
    const int warp = threadIdx.x >> 5;
    const int lane = threadIdx.x & 31;
    const int b = blockIdx.x * 8 + warp;
    const int idx = __ldg(&nidx[b]);
    const float s = __ldg(&g_ssp[idx]) + __ldg(&g_ssp[ROWS_PAD + idx]) +
                    __ldg(&g_ssp[2 * ROWS_PAD + idx]);
    const float inv = 1.f / fmaxf(sqrtf(s), 1e-12f);

    const float4* zp = reinterpret_cast<const float4*>(&g_Z[(size_t)idx * D_OUT]);
    float4* op = reinterpret_cast<float4*>(&out[(size_t)b * D_OUT]);
    float4 v0 = __ldg(&zp[lane]);
    float4 v1 = __ldg(&zp[lane + 32]);
    float4 v2 = __ldg(&zp[lane + 64]);
    v0.x *= inv; v0.y *= inv; v0.z *= inv; v0.w *= inv;
    v1.x *= inv; v1.y *= inv; v1.z *= inv; v1.w *= inv;
    v2.x *= inv; v2.y *= inv; v2.z *= inv; v2.w *= inv;
    op[lane]      = v0;
    op[lane + 32] = v1;
    op[lane + 64] = v2;
}

// ---------------------------------------------------------------------------
// Stream/event resources created once at static-init time.
// Two agg streams -> two groups aggregate concurrently (2x resident warps),
// one gemm stream consumes per-group completion events in order.
// ---------------------------------------------------------------------------
static cudaStream_t s_aggA, s_aggB, s_gemmS;
static cudaEvent_t  s_evRoot, s_evAgg[NGRP], s_evJoin;
struct _ResInit {
    _ResInit() {
        cudaStreamCreateWithFlags(&s_aggA,  cudaStreamNonBlocking);
        cudaStreamCreateWithFlags(&s_aggB,  cudaStreamNonBlocking);
        cudaStreamCreateWithFlags(&s_gemmS, cudaStreamNonBlocking);
        cudaEventCreateWithFlags(&s_evRoot, cudaEventDisableTiming);
        for (int g = 0; g < NGRP; g++)
            cudaEventCreateWithFlags(&s_evAgg[g], cudaEventDisableTiming);
        cudaEventCreateWithFlags(&s_evJoin, cudaEventDisableTiming);
        cudaFuncSetAttribute(gemm_hmma, cudaFuncAttributeMaxDynamicSharedMemorySize, SMEM_GEMM);
    }
};
static _ResInit s_resInit;

// ---------------------------------------------------------------------------
extern "C" void kernel_launch(void* const* d_in, const int* in_sizes, int n_in,
                              void* d_out, int out_size) {
    const int*   uniq = (const int*)d_in[0];
    const int*   adj  = (const int*)d_in[1];
    const int*   dis  = (const int*)d_in[2];
    const int*   nidx = (const int*)d_in[3];
    const float* feat = (const float*)d_in[4];
    const float* Ws   = (const float*)d_in[5];
    const float* Wa   = (const float*)d_in[6];
    const float* Wd   = (const float*)d_in[7];
    const float* bias = (const float*)d_in[8];
    const float* WC   = (const float*)d_in[9];
    const float* WCb  = (const float*)d_in[10];
    float* out = (float*)d_out;

    // fork from the (captured) legacy stream
    cudaEventRecord(s_evRoot, 0);
    cudaStreamWaitEvent(s_aggA,  s_evRoot, 0);
    cudaStreamWaitEvent(s_aggB,  s_evRoot, 0);
    cudaStreamWaitEvent(s_gemmS, s_evRoot, 0);

    // combine runs concurrently with agg on the gemm stream
    combine_kernel<<<49, 384, 0, s_gemmS>>>(Ws, Wa, Wd, WC, bias, WCb);

    // agg groups alternate between two streams (pairs run concurrently)
    for (int g = 0; g < NGRP; g++) {
        cudaStream_t st = (g & 1) ? s_aggB : s_aggA;
        int nodes = g_node0[g + 1] - g_node0[g];
        agg_kernel<<<nodes / 8, 256, 0, st>>>(uniq, adj, dis, feat, g_node0[g]);
        cudaEventRecord(s_evAgg[g], st);
    }
    // gemm groups on gemm stream, each gated on its agg group
    for (int g = 0; g < NGRP; g++) {
        int tiles = g_tile0[g + 1] - g_tile0[g];
        cudaStreamWaitEvent(s_gemmS, s_evAgg[g], 0);
        gemm_hmma<<<dim3(tiles, 3), 256, SMEM_GEMM, s_gemmS>>>(g_tile0[g]);
    }

    // join back to legacy stream, then gather
    cudaEventRecord(s_evJoin, s_gemmS);
    cudaStreamWaitEvent(0, s_evJoin, 0);
    gather_kernel<<<B_OUT / 8, 256>>>(nidx, out);
}

// round 10
// speedup vs baseline: 1.0747x; 1.0747x over previous
#include <cuda_runtime.h>
#include <cuda_bf16.h>
#include <math.h>
#include <stdint.h>

#define N_UNIQ 20000
#define D_IN   128
#define D_OUT  384
#define K_NB   32
#define B_OUT  40000

#define KP        768          // split-K storage: [hi 384 | lo 384]
#define ROWS_PAD  20096        // 157 * 128
#define NCHUNK    36           // 3 segments x 12 chunks of BK=32
#define NGRP      4

// row-group boundaries (nodes) and M-tile boundaries
static const int g_node0[NGRP + 1] = {0, 5120, 10240, 15360, 20000};
static const int g_tile0[NGRP + 1] = {0, 40, 80, 120, 157};

// ---------------- scratch (__device__ globals) ------------------------------
__device__ __align__(128) __nv_bfloat16 g_Xs[ROWS_PAD * KP];  // A, hi|lo
__device__ __align__(128) __nv_bfloat16 g_Bt[D_OUT * KP];     // B [n][k], hi|lo
__device__ __align__(128) float g_c[D_OUT];                   // fused bias
__device__ __align__(128) float g_Z[ROWS_PAD * D_OUT];        // unnormalized out
__device__ __align__(128) float g_ssp[3 * ROWS_PAD];          // per-(yslab,row) sum sq

// ---------------- helpers ----------------------------------------------------
__device__ __forceinline__ uint32_t smem_u32(const void* p) {
    uint32_t a;
    asm("{ .reg .u64 t; cvta.to.shared.u64 t, %1; cvt.u32.u64 %0, t; }" : "=r"(a) : "l"(p));
    return a;
}
#define LDMATRIX_X4(r0, r1, r2, r3, addr) \
    asm volatile("ldmatrix.sync.aligned.m8n8.x4.shared.b16 {%0,%1,%2,%3}, [%4];" \
                 : "=r"(r0), "=r"(r1), "=r"(r2), "=r"(r3) : "r"(addr))
#define MMA_16816(d, a, b0, b1) \
    asm volatile("mma.sync.aligned.m16n8k16.row.col.f32.bf16.bf16.f32 " \
                 "{%0,%1,%2,%3}, {%4,%5,%6,%7}, {%8,%9}, {%0,%1,%2,%3};" \
                 : "+f"((d)[0]), "+f"((d)[1]), "+f"((d)[2]), "+f"((d)[3]) \
                 : "r"((a)[0]), "r"((a)[1]), "r"((a)[2]), "r"((a)[3]), \
                   "r"(b0), "r"(b1))
#define CP_ASYNC_16(dst, src) \
    asm volatile("cp.async.cg.shared.global [%0], [%1], 16;" :: "r"(dst), "l"(src))
#define CP_COMMIT() asm volatile("cp.async.commit_group;" ::: "memory")
#define CP_WAIT2()  asm volatile("cp.async.wait_group 2;" ::: "memory")

// ---------------------------------------------------------------------------
// Kernel 1: fused weight (transposed [n][k], bf16 hi|lo split) + fused bias.
// ---------------------------------------------------------------------------
__global__ __launch_bounds__(384) void combine_kernel(const float* __restrict__ Ws,
                               const float* __restrict__ Wa,
                               const float* __restrict__ Wd,
                               const float* __restrict__ WC,
                               const float* __restrict__ bias,
                               const float* __restrict__ WCb) {
    int j = threadIdx.x;      // output col n (0..383)
    int rb = blockIdx.x;      // 0..47 = 8-row groups, 48 = bias
    if (rb < 48) {
        int r0 = rb * 8;
        int part = r0 >> 7;
        const float* W = (part == 0) ? Ws : ((part == 1) ? Wa : Wd);
        __shared__ float sW[8][128];
        for (int t = j; t < 1024; t += 384) {
            int q = t >> 7, o = t & 127;
            sW[q][o] = W[((r0 & 127) + q) * 128 + o];
        }
        __syncthreads();
        float acc[8] = {0.f, 0.f, 0.f, 0.f, 0.f, 0.f, 0.f, 0.f};
#pragma unroll 4
        for (int o = 0; o < 128; o++) {
            float wc = __ldg(&WC[(part * 128 + o) * D_OUT + j]);
#pragma unroll
            for (int q = 0; q < 8; q++) acc[q] += sW[q][o] * wc;
        }
#pragma unroll
        for (int q = 0; q < 8; q++) {
            __nv_bfloat16 hi = __float2bfloat16(acc[q]);
            __nv_bfloat16 lo = __float2bfloat16(acc[q] - __bfloat162float(hi));
            g_Bt[j * KP + r0 + q] = hi;
            g_Bt[j * KP + 384 + r0 + q] = lo;
        }
    } else {
        float acc = WCb[j];
        for (int i = 0; i < D_OUT; i++)
            acc += bias[i] * WC[i * D_OUT + j];
        g_c[j] = acc;
    }
}

// ---------------------------------------------------------------------------
// Kernel 2: aggregation, warp-per-node (R6-proven body).
// ---------------------------------------------------------------------------
__global__ __launch_bounds__(256) void agg_kernel(const int* __restrict__ uniq,
                                                  const int* __restrict__ adj,
                                                  const int* __restrict__ dis,
                                                  const float* __restrict__ feat,
                                                  int node0) {
    const int warp = threadIdx.x >> 5;
    const int lane = threadIdx.x & 31;
    const int n = node0 + blockIdx.x * 8 + warp;

    const int ia = __ldg(&adj[n * K_NB + lane]);
    const int id = __ldg(&dis[n * K_NB + lane]);
    const int iu = __ldg(&uniq[n]);

    const float4* f4 = reinterpret_cast<const float4*>(feat);

    float4 a = make_float4(0.f, 0.f, 0.f, 0.f);
    float4 b = make_float4(0.f, 0.f, 0.f, 0.f);
#pragma unroll
    for (int k = 0; k < K_NB; k++) {
        int ra = __shfl_sync(0xffffffffu, ia, k);
        int rd = __shfl_sync(0xffffffffu, id, k);
        float4 va = __ldg(&f4[(size_t)ra * 32 + lane]);
        float4 vb = __ldg(&f4[(size_t)rd * 32 + lane]);
        a.x += va.x; a.y += va.y; a.z += va.z; a.w += va.w;
        b.x += vb.x; b.y += vb.y; b.z += vb.z; b.w += vb.w;
    }
    float4 sf = __ldg(&f4[(size_t)iu * 32 + lane]);
    const float inv = 1.f / 32.f;
    a.x *= inv; a.y *= inv; a.z *= inv; a.w *= inv;
    b.x *= inv; b.y *= inv; b.z *= inv; b.w *= inv;

    __nv_bfloat16* row = &g_Xs[(size_t)n * KP];
    auto store_seg = [&](int base, float4 v) {
        __nv_bfloat16 h[4], l[4];
        float vv[4] = {v.x, v.y, v.z, v.w};
#pragma unroll
        for (int q = 0; q < 4; q++) {
            h[q] = __float2bfloat16(vv[q]);
            l[q] = __float2bfloat16(vv[q] - __bfloat162float(h[q]));
        }
        *reinterpret_cast<uint2*>(&row[base + lane * 4])       = *reinterpret_cast<uint2*>(h);
        *reinterpret_cast<uint2*>(&row[384 + base + lane * 4]) = *reinterpret_cast<uint2*>(l);
    };
    store_seg(0, sf);
    store_seg(128, a);
    store_seg(256, b);
}

// ---------------------------------------------------------------------------
// Kernel 3: HMMA GEMM, 4-stage cp.async pipeline. Grid (tiles_g, 3).
// ---------------------------------------------------------------------------
#define LDROW   80
#define STG     (128 * LDROW)     // 10240 B per operand stage
#define SMEM_GEMM (4 * 2 * STG)   // 81920

__global__ __launch_bounds__(256, 2) void gemm_hmma(int tile0) {
    extern __shared__ __align__(128) char dsm[];
    const uint32_t sbase = smem_u32(dsm);
    const uint32_t aarea = sbase;
    const uint32_t barea = sbase + 4 * STG;

    const int tid   = threadIdx.x;
    const int lane  = tid & 31;
    const int wid   = tid >> 5;
    const int warpM = wid & 3;
    const int warpN = wid >> 2;
    const int row0  = (tile0 + blockIdx.x) * 128;
    const int n0    = blockIdx.y * 128;

    float acc[2][8][4];
#pragma unroll
    for (int mt = 0; mt < 2; mt++)
#pragma unroll
        for (int nt = 0; nt < 8; nt++)
#pragma unroll
            for (int q = 0; q < 4; q++) acc[mt][nt][q] = 0.f;

    const int ldr = tid >> 2;   // 0..63
    const int ldu = tid & 3;    // 0..3

    auto issue_stage = [&](int c) {
        int s = c & 3;
        int seg = c / 12, i = c % 12;
        int abase = ((seg == 1) ? 384 : 0) + i * 32;
        int bbase = ((seg == 2) ? 384 : 0) + i * 32;
        uint32_t da = aarea + s * STG;
        uint32_t db = barea + s * STG;
#pragma unroll
        for (int it = 0; it < 2; it++) {
            int r = ldr + it * 64;
            CP_ASYNC_16(da + r * LDROW + ldu * 16,
                        (const void*)&g_Xs[(size_t)(row0 + r) * KP + abase + ldu * 8]);
            CP_ASYNC_16(db + r * LDROW + ldu * 16,
                        (const void*)&g_Bt[(size_t)(n0 + r) * KP + bbase + ldu * 8]);
        }
    };

    const int lq = lane >> 3, lr = lane & 7;
    const int a_mrow = warpM * 32 + (lq & 1) * 8 + lr;
    const int a_koff = (lq >> 1) * 8;
    const int b_nrow = warpN * 64 + (lq >> 1) * 8 + lr;
    const int b_koff = (lq & 1) * 8;

#pragma unroll
    for (int s = 0; s < 3; s++) { issue_stage(s); CP_COMMIT(); }

    for (int c = 0; c < NCHUNK; c++) {
        CP_WAIT2();
        __syncthreads();
        if (c + 3 < NCHUNK) issue_stage(c + 3);
        CP_COMMIT();

        const int s = c & 3;
        const uint32_t abuf = aarea + s * STG;
        const uint32_t bbuf = barea + s * STG;
#pragma unroll
        for (int ks = 0; ks < 2; ks++) {
            uint32_t a[2][4];
#pragma unroll
            for (int mt = 0; mt < 2; mt++) {
                uint32_t addr = abuf + (a_mrow + mt * 16) * LDROW + (ks * 16 + a_koff) * 2;
                LDMATRIX_X4(a[mt][0], a[mt][1], a[mt][2], a[mt][3], addr);
            }
            uint32_t b[4][4];
#pragma unroll
            for (int np = 0; np < 4; np++) {
                uint32_t addr = bbuf + (b_nrow + np * 16) * LDROW + (ks * 16 + b_koff) * 2;
                LDMATRIX_X4(b[np][0], b[np][1], b[np][2], b[np][3], addr);
            }
#pragma unroll
            for (int mt = 0; mt < 2; mt++)
#pragma unroll
                for (int np = 0; np < 4; np++) {
                    MMA_16816(acc[mt][np * 2 + 0], a[mt], b[np][0], b[np][1]);
                    MMA_16816(acc[mt][np * 2 + 1], a[mt], b[np][2], b[np][3]);
                }
        }
    }

    // ---- epilogue ----
    const int g  = lane >> 2;
    const int cq = lane & 3;
    float ssA[2], ssB[2];
#pragma unroll
    for (int mt = 0; mt < 2; mt++) {
        const int rbase = row0 + warpM * 32 + mt * 16;
        float ss0 = 0.f, ss1 = 0.f;
#pragma unroll
        for (int nt = 0; nt < 8; nt++) {
            int col = n0 + warpN * 64 + nt * 8 + cq * 2;
            float b0 = __ldg(&g_c[col]);
            float b1 = __ldg(&g_c[col + 1]);
            float z0 = acc[mt][nt][0] + b0; z0 = (z0 >= 0.f) ? z0 : 0.2f * z0;
            float z1 = acc[mt][nt][1] + b1; z1 = (z1 >= 0.f) ? z1 : 0.2f * z1;
            float z2 = acc[mt][nt][2] + b0; z2 = (z2 >= 0.f) ? z2 : 0.2f * z2;
            float z3 = acc[mt][nt][3] + b1; z3 = (z3 >= 0.f) ? z3 : 0.2f * z3;
            *reinterpret_cast<float2*>(&g_Z[(size_t)(rbase + g) * D_OUT + col])     = make_float2(z0, z1);
            *reinterpret_cast<float2*>(&g_Z[(size_t)(rbase + g + 8) * D_OUT + col]) = make_float2(z2, z3);
            ss0 += z0 * z0 + z1 * z1;
            ss1 += z2 * z2 + z3 * z3;
        }
        ss0 += __shfl_xor_sync(0xffffffffu, ss0, 1);
        ss0 += __shfl_xor_sync(0xffffffffu, ss0, 2);
        ss1 += __shfl_xor_sync(0xffffffffu, ss1, 1);
        ss1 += __shfl_xor_sync(0xffffffffu, ss1, 2);
        ssA[mt] = ss0;
        ssB[mt] = ss1;
    }
    __syncthreads();
    float* s_ss = reinterpret_cast<float*>(dsm);
    if (tid < 128) s_ss[tid] = 0.f;
    __syncthreads();
    if (cq == 0) {
#pragma unroll
        for (int mt = 0; mt < 2; mt++) {
            atomicAdd(&s_ss[warpM * 32 + mt * 16 + g],     ssA[mt]);
            atomicAdd(&s_ss[warpM * 32 + mt * 16 + 8 + g], ssB[mt]);
        }
    }
    __syncthreads();
    if (tid < 128) g_ssp[(size_t)blockIdx.y * ROWS_PAD + row0 + tid] = s_ss[tid];
}

// ---------------------------------------------------------------------------
// Kernel 4: normalize + batch gather. Warp per output row, MLP 3.
// ---------------------------------------------------------------------------
__global__ __launch_bounds__(256) void gather_kernel(const int* __restrict__ nidx,
                                                     float* __restrict__ out) {
    const int warp = threadIdx.x >> 5;
    const int lane = threadIdx.x & 31;
    const int b = blockIdx.x * 8 + warp;
    const int idx = __ldg(&nidx[b]);
    const float s = __ldg(&g_ssp[idx]) + __ldg(&g_ssp[ROWS_PAD + idx]) +
                    __ldg(&g_ssp[2 * ROWS_PAD + idx]);
    const float inv = 1.f / fmaxf(sqrtf(s), 1e-12f);

    const float4* zp = reinterpret_cast<const float4*>(&g_Z[(size_t)idx * D_OUT]);
    float4* op = reinterpret_cast<float4*>(&out[(size_t)b * D_OUT]);
    float4 v0 = __ldg(&zp[lane]);
    float4 v1 = __ldg(&zp[lane + 32]);
    float4 v2 = __ldg(&zp[lane + 64]);
    v0.x *= inv; v0.y *= inv; v0.z *= inv; v0.w *= inv;
    v1.x *= inv; v1.y *= inv; v1.z *= inv; v1.w *= inv;
    v2.x *= inv; v2.y *= inv; v2.z *= inv; v2.w *= inv;
    op[lane]      = v0;
    op[lane + 32] = v1;
    op[lane + 64] = v2;
}

// ---------------------------------------------------------------------------
// Stream/event resources created once at static-init time.
// gemm stream at GREATEST priority (fallback: plain nonblocking streams if the
// priority API is unavailable) so gemm CTAs co-reside with the DRAM-bound agg
// kernel instead of queueing behind its 640-CTA backlog.
// ---------------------------------------------------------------------------
static cudaStream_t s_aggS, s_gemmS;
static cudaEvent_t  s_evRoot, s_evAgg[NGRP], s_evJoin;
struct _ResInit {
    _ResInit() {
        int lo = 0, hi = 0;
        cudaError_t e = cudaDeviceGetStreamPriorityRange(&lo, &hi);
        if (e == cudaSuccess && lo != hi) {
            cudaStreamCreateWithPriority(&s_aggS,  cudaStreamNonBlocking, lo);
            cudaStreamCreateWithPriority(&s_gemmS, cudaStreamNonBlocking, hi);
        } else {
            cudaStreamCreateWithFlags(&s_aggS,  cudaStreamNonBlocking);
            cudaStreamCreateWithFlags(&s_gemmS, cudaStreamNonBlocking);
        }
        cudaEventCreateWithFlags(&s_evRoot, cudaEventDisableTiming);
        for (int g = 0; g < NGRP; g++)
            cudaEventCreateWithFlags(&s_evAgg[g], cudaEventDisableTiming);
        cudaEventCreateWithFlags(&s_evJoin, cudaEventDisableTiming);
        cudaFuncSetAttribute(gemm_hmma, cudaFuncAttributeMaxDynamicSharedMemorySize, SMEM_GEMM);
    }
};
static _ResInit s_resInit;

// ---------------------------------------------------------------------------
extern "C" void kernel_launch(void* const* d_in, const int* in_sizes, int n_in,
                              void* d_out, int out_size) {
    const int*   uniq = (const int*)d_in[0];
    const int*   adj  = (const int*)d_in[1];
    const int*   dis  = (const int*)d_in[2];
    const int*   nidx = (const int*)d_in[3];
    const float* feat = (const float*)d_in[4];
    const float* Ws   = (const float*)d_in[5];
    const float* Wa   = (const float*)d_in[6];
    const float* Wd   = (const float*)d_in[7];
    const float* bias = (const float*)d_in[8];
    const float* WC   = (const float*)d_in[9];
    const float* WCb  = (const float*)d_in[10];
    float* out = (float*)d_out;

    // fork from the (captured) legacy stream
    cudaEventRecord(s_evRoot, 0);
    cudaStreamWaitEvent(s_aggS,  s_evRoot, 0);
    cudaStreamWaitEvent(s_gemmS, s_evRoot, 0);

    // combine runs concurrently with agg on the gemm stream
    combine_kernel<<<49, 384, 0, s_gemmS>>>(Ws, Wa, Wd, WC, bias, WCb);

    // agg groups on the (low-priority) agg stream
    for (int g = 0; g < NGRP; g++) {
        int nodes = g_node0[g + 1] - g_node0[g];
        agg_kernel<<<nodes / 8, 256, 0, s_aggS>>>(uniq, adj, dis, feat, g_node0[g]);
        cudaEventRecord(s_evAgg[g], s_aggS);
    }
    // gemm groups on the (high-priority) gemm stream, each gated on its agg group
    for (int g = 0; g < NGRP; g++) {
        int tiles = g_tile0[g + 1] - g_tile0[g];
        cudaStreamWaitEvent(s_gemmS, s_evAgg[g], 0);
        gemm_hmma<<<dim3(tiles, 3), 256, SMEM_GEMM, s_gemmS>>>(g_tile0[g]);
    }

    // join back to legacy stream, then gather
    cudaEventRecord(s_evJoin, s_gemmS);
    cudaStreamWaitEvent(0, s_evJoin, 0);
    gather_kernel<<<B_OUT / 8, 256>>>(nidx, out);
}